// round 4
// baseline (speedup 1.0000x reference)
#include <cuda_runtime.h>

#define NJ   24          // joints per frame
#define FPB  8           // frames per block
#define TPB  (NJ * FPB)  // 192 threads, one node per thread
#define NEG  0.2f        // LeakyReLU slope

__constant__ int c_parent[NJ] = {-1,0,0,0,1,2,3,4,5,6,7,8,9,9,9,12,13,14,16,17,18,19,20,21};

// packed fp32x2 FMA (Blackwell): d = a*b + d elementwise on two packed f32
__device__ __forceinline__ void fma2(unsigned long long &d, unsigned long long a, unsigned long long b) {
    asm("fma.rn.f32x2 %0, %1, %2, %0;" : "+l"(d) : "l"(a), "l"(b));
}
__device__ __forceinline__ unsigned long long pack2(float x) {
    unsigned long long r;
    asm("mov.b64 %0, {%1, %1};" : "=l"(r) : "f"(x));
    return r;
}
__device__ __forceinline__ float2 unpack2(unsigned long long v) {
    float2 f;
    asm("mov.b64 {%0, %1}, %2;" : "=f"(f.x), "=f"(f.y) : "l"(v));
    return f;
}

__global__ __launch_bounds__(TPB)
void gat_encoder_kernel(const float* __restrict__ src,
                        const float* __restrict__ Wpre,   // (3,24)
                        const float* __restrict__ bpre,   // (24)
                        const float* __restrict__ Wg,     // (24,24)
                        const float* __restrict__ attS,   // (3,8)
                        const float* __restrict__ attD,   // (3,8)
                        const float* __restrict__ bg,     // (24)
                        float* __restrict__ out)
{
    __shared__ __align__(16) float sWpre[3 * 24];
    __shared__ __align__(16) float sbpre[24];
    __shared__ __align__(16) float sWg[24 * 24];
    __shared__ __align__(16) float sAttS[24];
    __shared__ __align__(16) float sAttD[24];
    __shared__ __align__(16) float sbg[24];
    __shared__ float sH[TPB * 27];   // per node: h[24] + a_src[3]; stride 27 (coprime w/ 32) -> conflict-free

    const int tid = threadIdx.x;

    // ---- stage weights into shared ----
    if (tid < 72) sWpre[tid] = Wpre[tid];
    if (tid < 24) {
        sbpre[tid] = bpre[tid];
        sAttS[tid] = attS[tid];
        sAttD[tid] = attD[tid];
        sbg[tid]   = bg[tid];
    }
    for (int i = tid; i < 576; i += TPB) sWg[i] = Wg[i];

    const int node = blockIdx.x * TPB + tid;   // global node index (block = 8 whole frames)
    const int j = tid % NJ;                    // joint within frame

    // ---- load input (coalesced: 3 consecutive floats per node) ----
    const float* sp = src + (size_t)node * 3;
    const float in0 = sp[0], in1 = sp[1], in2 = sp[2];

    __syncthreads();   // weights ready

    // ---- phase 1: x = relu(in @ Wpre + bpre), packed pairs ----
    unsigned long long xa[12];
    {
        const unsigned long long* bp2 = (const unsigned long long*)sbpre;
        #pragma unroll
        for (int m = 0; m < 12; m++) xa[m] = bp2[m];
        const unsigned long long p0 = pack2(in0);
        const unsigned long long p1 = pack2(in1);
        const unsigned long long p2 = pack2(in2);
        const ulonglong2* w0 = (const ulonglong2*)(sWpre);
        const ulonglong2* w1 = (const ulonglong2*)(sWpre + 24);
        const ulonglong2* w2 = (const ulonglong2*)(sWpre + 48);
        #pragma unroll
        for (int q = 0; q < 6; q++) {
            ulonglong2 a = w0[q], b = w1[q], c = w2[q];
            fma2(xa[2*q],   p0, a.x);  fma2(xa[2*q+1], p0, a.y);
            fma2(xa[2*q],   p1, b.x);  fma2(xa[2*q+1], p1, b.y);
            fma2(xa[2*q],   p2, c.x);  fma2(xa[2*q+1], p2, c.y);
        }
    }
    float x[24];
    #pragma unroll
    for (int m = 0; m < 12; m++) {
        float2 f = unpack2(xa[m]);
        x[2*m]   = fmaxf(f.x, 0.0f);
        x[2*m+1] = fmaxf(f.y, 0.0f);
    }

    // ---- phase 2: h = x @ Wg (no bias, no relu here), packed pairs ----
    unsigned long long h2[12];
    #pragma unroll
    for (int m = 0; m < 12; m++) h2[m] = 0ull;
    #pragma unroll
    for (int k = 0; k < 24; k++) {
        const unsigned long long xx = pack2(x[k]);
        const ulonglong2* wr = (const ulonglong2*)(sWg + k * 24);
        #pragma unroll
        for (int q = 0; q < 6; q++) {
            ulonglong2 w = wr[q];      // 4 weights = 2 packed pairs (LDS.128 broadcast)
            fma2(h2[2*q],     xx, w.x);
            fma2(h2[2*q + 1], xx, w.y);
        }
    }
    float h[24];
    #pragma unroll
    for (int m = 0; m < 12; m++) {
        float2 f = unpack2(h2[m]);
        h[2*m] = f.x; h[2*m+1] = f.y;
    }

    // ---- attention dots: a_src/a_dst per head ----
    float as_[3], ad_[3];
    #pragma unroll
    for (int hh = 0; hh < 3; hh++) {
        float s = 0.0f, d = 0.0f;
        #pragma unroll
        for (int o = 0; o < 8; o++) {
            const float hv = h[hh * 8 + o];
            s = fmaf(hv, sAttS[hh * 8 + o], s);
            d = fmaf(hv, sAttD[hh * 8 + o], d);
        }
        as_[hh] = s; ad_[hh] = d;
    }

    // ---- publish h + a_src for children ----
    {
        float* myH = sH + tid * 27;
        #pragma unroll
        for (int c = 0; c < 24; c++) myH[c] = h[c];
        myH[24] = as_[0]; myH[25] = as_[1]; myH[26] = as_[2];
    }
    __syncthreads();

    // ---- 2-edge segment softmax (self-loop + parent edge) ----
    const int par = c_parent[j];
    const bool hasPar = (par >= 0);
    const int pt = (tid - j) + (hasPar ? par : 0);   // parent's thread index in-block
    const float* pH = sH + pt * 27;

    float aS[3], aP[3];
    #pragma unroll
    for (int hh = 0; hh < 3; hh++) {
        float es = as_[hh] + ad_[hh];
        es = es >= 0.0f ? es : NEG * es;             // leaky_relu
        float ep = pH[24 + hh] + ad_[hh];
        ep = ep >= 0.0f ? ep : NEG * ep;
        ep = hasPar ? ep : -1e30f;                   // root: only self-loop
        const float mx = fmaxf(es, ep);
        const float ws = __expf(es - mx);
        const float wp = __expf(ep - mx);
        const float inv = __fdividef(1.0f, ws + wp);
        aS[hh] = ws * inv;
        aP[hh] = wp * inv;
    }

    // ---- aggregate, bias, relu, store (coalesced float4) ----
    float4* o4 = (float4*)(out + (size_t)node * 24);
    #pragma unroll
    for (int q = 0; q < 6; q++) {
        float4 r;
        #pragma unroll
        for (int i = 0; i < 4; i++) {
            const int c = q * 4 + i;
            const int hh = c >> 3;
            float t = fmaf(aS[hh], h[c], fmaf(aP[hh], pH[c], sbg[c]));
            t = fmaxf(t, 0.0f);
            if (i == 0) r.x = t; else if (i == 1) r.y = t; else if (i == 2) r.z = t; else r.w = t;
        }
        o4[q] = r;
    }
}

extern "C" void kernel_launch(void* const* d_in, const int* in_sizes, int n_in,
                              void* d_out, int out_size) {
    (void)n_in; (void)out_size;
    const float* src  = (const float*)d_in[0];
    const float* Wpre = (const float*)d_in[1];
    const float* bpre = (const float*)d_in[2];
    const float* Wg   = (const float*)d_in[3];
    const float* attS = (const float*)d_in[4];
    const float* attD = (const float*)d_in[5];
    const float* bg   = (const float*)d_in[6];

    const int nodes  = in_sizes[0] / 3;        // 3,145,728
    const int blocks = nodes / TPB;            // 16,384 (exact)

    gat_encoder_kernel<<<blocks, TPB>>>(src, Wpre, bpre, Wg, attS, attD, bg, (float*)d_out);
}

// round 5
// speedup vs baseline: 1.1415x; 1.1415x over previous
#include <cuda_runtime.h>

#define NJ   24
#define TPB  192
#define NPB  (TPB * 2)      // 384 nodes (= 16 frames) per block, 2 per thread
#define NEG  0.2f

typedef unsigned long long ull;

__constant__ int c_parent[NJ] = {-1,0,0,0,1,2,3,4,5,6,7,8,9,9,9,12,13,14,16,17,18,19,20,21};
#define PARENT_MASK 0x3F73FFu   // joints that are some child's parent (others skip publish)

__device__ __forceinline__ void fma2(ull &d, ull a, ull b) {
    asm("fma.rn.f32x2 %0, %1, %2, %0;" : "+l"(d) : "l"(a), "l"(b));
}
__device__ __forceinline__ ull pack2(float x) {
    ull r; asm("mov.b64 %0, {%1, %1};" : "=l"(r) : "f"(x)); return r;
}
__device__ __forceinline__ ull packf2(float lo, float hi) {
    ull r; asm("mov.b64 %0, {%1, %2};" : "=l"(r) : "f"(lo), "f"(hi)); return r;
}
__device__ __forceinline__ float2 unpack2(ull v) {
    float2 f; asm("mov.b64 {%0, %1}, %2;" : "=f"(f.x), "=f"(f.y) : "l"(v)); return f;
}

// Per-node epilogue: 2-edge softmax (self + parent) + aggregate + bias + relu + store
__device__ __forceinline__ void finish_node(const ull* __restrict__ h2,
                                            const float* __restrict__ as_,
                                            const float* __restrict__ ad_,
                                            const float* __restrict__ prow,
                                            bool hasPar,
                                            const ulonglong2* __restrict__ bg2,
                                            float* __restrict__ outp)
{
    const ulonglong2* p2 = (const ulonglong2*)prow;
    ulonglong2 pr[7];
    #pragma unroll
    for (int q = 0; q < 7; q++) pr[q] = p2[q];       // parent h[24] + a_src[3] (+pad)

    float2 pa01 = unpack2(pr[6].x);
    float2 pa2x = unpack2(pr[6].y);
    const float pas[3] = {pa01.x, pa01.y, pa2x.x};

    float aS[3], aP[3];
    #pragma unroll
    for (int hh = 0; hh < 3; hh++) {
        float es = as_[hh] + ad_[hh];
        es = es >= 0.0f ? es : NEG * es;
        float ep = pas[hh] + ad_[hh];
        ep = ep >= 0.0f ? ep : NEG * ep;
        ep = hasPar ? ep : -1e30f;
        const float mx  = fmaxf(es, ep);
        const float ws  = __expf(es - mx);
        const float wp  = __expf(ep - mx);
        const float inv = __fdividef(1.0f, ws + wp);
        aS[hh] = ws * inv;
        aP[hh] = hasPar ? wp * inv : 0.0f;
    }

    float4* o4 = (float4*)outp;
    #pragma unroll
    for (int q = 0; q < 6; q++) {                     // channels 4q..4q+3, head = q/2
        const int hh = q >> 1;
        const ull s2 = pack2(aS[hh]);
        const ull p2k = pack2(aP[hh]);
        ull r0 = bg2[q].x, r1 = bg2[q].y;
        fma2(r0, s2, h2[2*q]);     fma2(r0, p2k, pr[q].x);
        fma2(r1, s2, h2[2*q + 1]); fma2(r1, p2k, pr[q].y);
        float2 f0 = unpack2(r0), f1 = unpack2(r1);
        float4 v;
        v.x = fmaxf(f0.x, 0.0f); v.y = fmaxf(f0.y, 0.0f);
        v.z = fmaxf(f1.x, 0.0f); v.w = fmaxf(f1.y, 0.0f);
        o4[q] = v;
    }
}

__global__ __launch_bounds__(TPB, 2)
void gat_encoder_kernel(const float* __restrict__ src,
                        const float* __restrict__ Wpre,
                        const float* __restrict__ bpre,
                        const float* __restrict__ Wg,
                        const float* __restrict__ attS,
                        const float* __restrict__ attD,
                        const float* __restrict__ bg,
                        float* __restrict__ out)
{
    __shared__ __align__(16) float sWpre[72];
    __shared__ __align__(16) float sbpre[24];
    __shared__ __align__(16) float sWg[576];
    __shared__ __align__(16) float sAttS[24];
    __shared__ __align__(16) float sAttD[24];
    __shared__ __align__(16) float sbg[24];
    __shared__ __align__(16) float sH[NPB * 28];   // 28-float rows: h[24] + a_src[3] + pad

    const int t = threadIdx.x;

    if (t < 72) sWpre[t] = Wpre[t];
    if (t < 24) {
        sbpre[t] = bpre[t];
        sAttS[t] = attS[t];
        sAttD[t] = attD[t];
        sbg[t]   = bg[t];
    }
    for (int i = t; i < 576; i += TPB) sWg[i] = Wg[i];

    const size_t n0 = (size_t)blockIdx.x * NPB + t;
    const size_t n1 = n0 + TPB;
    const int j = t % NJ;                          // same joint for both nodes

    const float* s0 = src + n0 * 3;
    const float* s1 = src + n1 * 3;
    const float ia0 = s0[0], ia1 = s0[1], ia2 = s0[2];
    const float ib0 = s1[0], ib1 = s1[1], ib2 = s1[2];

    __syncthreads();

    // ---- phase 1: x = relu(in @ Wpre + bpre), both nodes, shared weight loads ----
    ull xa[12], xb[12];
    {
        const ull pa0 = pack2(ia0), pa1 = pack2(ia1), pa2 = pack2(ia2);
        const ull pb0 = pack2(ib0), pb1 = pack2(ib1), pb2 = pack2(ib2);
        const ulonglong2* w0 = (const ulonglong2*)(sWpre);
        const ulonglong2* w1 = (const ulonglong2*)(sWpre + 24);
        const ulonglong2* w2 = (const ulonglong2*)(sWpre + 48);
        const ulonglong2* bb = (const ulonglong2*)(sbpre);
        #pragma unroll
        for (int q = 0; q < 6; q++) {
            const ulonglong2 wa = w0[q], wbq = w1[q], wc = w2[q], bq = bb[q];
            xa[2*q] = bq.x; xa[2*q+1] = bq.y;
            xb[2*q] = bq.x; xb[2*q+1] = bq.y;
            fma2(xa[2*q], pa0, wa.x);  fma2(xa[2*q+1], pa0, wa.y);
            fma2(xb[2*q], pb0, wa.x);  fma2(xb[2*q+1], pb0, wa.y);
            fma2(xa[2*q], pa1, wbq.x); fma2(xa[2*q+1], pa1, wbq.y);
            fma2(xb[2*q], pb1, wbq.x); fma2(xb[2*q+1], pb1, wbq.y);
            fma2(xa[2*q], pa2, wc.x);  fma2(xa[2*q+1], pa2, wc.y);
            fma2(xb[2*q], pb2, wc.x);  fma2(xb[2*q+1], pb2, wc.y);
        }
    }
    float x0[24], x1[24];
    #pragma unroll
    for (int m = 0; m < 12; m++) {
        float2 fa = unpack2(xa[m]);
        float2 fb = unpack2(xb[m]);
        x0[2*m]   = fmaxf(fa.x, 0.0f);  x0[2*m+1] = fmaxf(fa.y, 0.0f);
        x1[2*m]   = fmaxf(fb.x, 0.0f);  x1[2*m+1] = fmaxf(fb.y, 0.0f);
    }

    // ---- phase 2: h = x @ Wg, weight loads amortized across both nodes ----
    ull hA[12], hB[12];
    #pragma unroll
    for (int m = 0; m < 12; m++) { hA[m] = 0ull; hB[m] = 0ull; }
    #pragma unroll
    for (int k = 0; k < 24; k++) {
        const ull pA = pack2(x0[k]);
        const ull pB = pack2(x1[k]);
        const ulonglong2* wr = (const ulonglong2*)(sWg + k * 24);
        #pragma unroll
        for (int q = 0; q < 6; q++) {
            const ulonglong2 w = wr[q];
            fma2(hA[2*q],     pA, w.x);
            fma2(hA[2*q + 1], pA, w.y);
            fma2(hB[2*q],     pB, w.x);
            fma2(hB[2*q + 1], pB, w.y);
        }
    }

    // ---- attention dots (packed, att vectors loaded once for both nodes) ----
    float asA[3], adA[3], asB[3], adB[3];
    {
        const ulonglong2* S2 = (const ulonglong2*)sAttS;
        const ulonglong2* D2 = (const ulonglong2*)sAttD;
        #pragma unroll
        for (int hh = 0; hh < 3; hh++) {
            const ulonglong2 s01 = S2[2*hh], s23 = S2[2*hh + 1];
            const ulonglong2 d01 = D2[2*hh], d23 = D2[2*hh + 1];
            ull aSA = 0ull, aDA = 0ull, aSB = 0ull, aDB = 0ull;
            fma2(aSA, hA[4*hh],   s01.x); fma2(aSA, hA[4*hh+1], s01.y);
            fma2(aSA, hA[4*hh+2], s23.x); fma2(aSA, hA[4*hh+3], s23.y);
            fma2(aDA, hA[4*hh],   d01.x); fma2(aDA, hA[4*hh+1], d01.y);
            fma2(aDA, hA[4*hh+2], d23.x); fma2(aDA, hA[4*hh+3], d23.y);
            fma2(aSB, hB[4*hh],   s01.x); fma2(aSB, hB[4*hh+1], s01.y);
            fma2(aSB, hB[4*hh+2], s23.x); fma2(aSB, hB[4*hh+3], s23.y);
            fma2(aDB, hB[4*hh],   d01.x); fma2(aDB, hB[4*hh+1], d01.y);
            fma2(aDB, hB[4*hh+2], d23.x); fma2(aDB, hB[4*hh+3], d23.y);
            float2 f;
            f = unpack2(aSA); asA[hh] = f.x + f.y;
            f = unpack2(aDA); adA[hh] = f.x + f.y;
            f = unpack2(aSB); asB[hh] = f.x + f.y;
            f = unpack2(aDB); adB[hh] = f.x + f.y;
        }
    }

    // ---- publish h + a_src (only joints that have children) ----
    if ((PARENT_MASK >> j) & 1u) {
        ulonglong2* r0 = (ulonglong2*)(sH + t * 28);
        ulonglong2* r1 = (ulonglong2*)(sH + (t + TPB) * 28);
        #pragma unroll
        for (int q = 0; q < 6; q++) {
            ulonglong2 va; va.x = hA[2*q]; va.y = hA[2*q + 1]; r0[q] = va;
            ulonglong2 vb; vb.x = hB[2*q]; vb.y = hB[2*q + 1]; r1[q] = vb;
        }
        ulonglong2 ta; ta.x = packf2(asA[0], asA[1]); ta.y = packf2(asA[2], 0.0f); r0[6] = ta;
        ulonglong2 tb; tb.x = packf2(asB[0], asB[1]); tb.y = packf2(asB[2], 0.0f); r1[6] = tb;
    }
    __syncthreads();

    // ---- softmax over {self, parent} + aggregate + store ----
    const int par = c_parent[j];
    const bool hasPar = (par >= 0);
    const int pt = (t - j) + (hasPar ? par : 0);   // root reads own (published) row, weight 0

    const ulonglong2* bg2 = (const ulonglong2*)sbg;
    finish_node(hA, asA, adA, sH + pt * 28,         hasPar, bg2, out + n0 * 24);
    finish_node(hB, asB, adB, sH + (pt + TPB) * 28, hasPar, bg2, out + n1 * 24);
}

extern "C" void kernel_launch(void* const* d_in, const int* in_sizes, int n_in,
                              void* d_out, int out_size) {
    (void)n_in; (void)out_size;
    const float* src  = (const float*)d_in[0];
    const float* Wpre = (const float*)d_in[1];
    const float* bpre = (const float*)d_in[2];
    const float* Wg   = (const float*)d_in[3];
    const float* attS = (const float*)d_in[4];
    const float* attD = (const float*)d_in[5];
    const float* bg   = (const float*)d_in[6];

    const int nodes  = in_sizes[0] / 3;   // 3,145,728
    const int blocks = nodes / NPB;       // 8,192 (exact)

    gat_encoder_kernel<<<blocks, TPB>>>(src, Wpre, bpre, Wg, attS, attD, bg, (float*)d_out);
}

// round 6
// speedup vs baseline: 1.2359x; 1.0827x over previous
#include <cuda_runtime.h>

#define NJ   24
#define TPB  192
#define NG   64            // node-groups per block (TPB/3)
#define NPT  6             // nodes per thread
#define NPB  (NG * NPT)    // 384 nodes (=16 frames) per block
#define RS   28            // shared row stride (floats), 28 coprime-ish padding, 16B-aligned rows
#define NEG  0.2f

typedef unsigned long long ull;

__constant__ int c_parent[NJ] = {-1,0,0,0,1,2,3,4,5,6,7,8,9,9,9,12,13,14,16,17,18,19,20,21};
#define PARENT_MASK 0x3F73FFu

__device__ __forceinline__ void fma2(ull &d, ull a, ull b) {
    asm("fma.rn.f32x2 %0, %1, %2, %0;" : "+l"(d) : "l"(a), "l"(b));
}
__device__ __forceinline__ ull pack2(float x) {
    ull r; asm("mov.b64 %0, {%1, %1};" : "=l"(r) : "f"(x)); return r;
}
__device__ __forceinline__ ull packf2(float lo, float hi) {
    ull r; asm("mov.b64 %0, {%1, %2};" : "=l"(r) : "f"(lo), "f"(hi)); return r;
}
__device__ __forceinline__ float2 unpack2(ull v) {
    float2 f; asm("mov.b64 {%0, %1}, %2;" : "=f"(f.x), "=f"(f.y) : "l"(v)); return f;
}

__global__ __launch_bounds__(TPB, 3)
void gat_encoder_kernel(const float* __restrict__ src,
                        const float* __restrict__ Wpre,   // (3,24)
                        const float* __restrict__ bpre,   // (24)
                        const float* __restrict__ Wg,     // (24,24)
                        const float* __restrict__ attS,   // (3,8)
                        const float* __restrict__ attD,   // (3,8)
                        const float* __restrict__ bg,     // (24)
                        float* __restrict__ out)
{
    __shared__ __align__(16) float sWpre[72];
    __shared__ __align__(16) float sbpre[24];
    __shared__ __align__(16) float sWg[576];
    __shared__ __align__(16) float sAttS[24];
    __shared__ __align__(16) float sAttD[24];
    __shared__ __align__(16) float sbg[24];
    __shared__ __align__(16) float sX[NPB * RS];   // x rows, later h[24]+a_src[3] rows

    const int t  = threadIdx.x;
    const int cg = t % 3;          // head index: channels 8cg..8cg+7
    const int g  = t / 3;          // node group 0..63

    if (t < 72) sWpre[t] = Wpre[t];
    if (t < 24) {
        sbpre[t] = bpre[t];
        sAttS[t] = attS[t];
        sAttD[t] = attD[t];
        sbg[t]   = bg[t];
    }
    for (int i = t; i < 576; i += TPB) sWg[i] = Wg[i];

    const size_t base = (size_t)blockIdx.x * NPB;

    // ---- load inputs for my 6 nodes (coalesced; cg-triples merge in-warp) ----
    float in0[NPT], in1[NPT], in2[NPT];
    #pragma unroll
    for (int i = 0; i < NPT; i++) {
        const float* p = src + (base + (size_t)(g + 64 * i)) * 3;
        in0[i] = p[0]; in1[i] = p[1]; in2[i] = p[2];
    }

    __syncthreads();

    // ---- phase 1: x[n][8cg..8cg+7] = relu(in @ Wpre + b), write to shared ----
    {
        const ulonglong2 w00 = ((const ulonglong2*)(sWpre     ))[2*cg];
        const ulonglong2 w01 = ((const ulonglong2*)(sWpre     ))[2*cg + 1];
        const ulonglong2 w10 = ((const ulonglong2*)(sWpre + 24))[2*cg];
        const ulonglong2 w11 = ((const ulonglong2*)(sWpre + 24))[2*cg + 1];
        const ulonglong2 w20 = ((const ulonglong2*)(sWpre + 48))[2*cg];
        const ulonglong2 w21 = ((const ulonglong2*)(sWpre + 48))[2*cg + 1];
        const ulonglong2 b0  = ((const ulonglong2*)(sbpre     ))[2*cg];
        const ulonglong2 b1  = ((const ulonglong2*)(sbpre     ))[2*cg + 1];
        #pragma unroll
        for (int i = 0; i < NPT; i++) {
            ull a0 = b0.x, a1 = b0.y, a2 = b1.x, a3 = b1.y;
            const ull p0 = pack2(in0[i]), p1 = pack2(in1[i]), p2 = pack2(in2[i]);
            fma2(a0, p0, w00.x); fma2(a1, p0, w00.y); fma2(a2, p0, w01.x); fma2(a3, p0, w01.y);
            fma2(a0, p1, w10.x); fma2(a1, p1, w10.y); fma2(a2, p1, w11.x); fma2(a3, p1, w11.y);
            fma2(a0, p2, w20.x); fma2(a1, p2, w20.y); fma2(a2, p2, w21.x); fma2(a3, p2, w21.y);
            float2 f0 = unpack2(a0), f1 = unpack2(a1), f2 = unpack2(a2), f3 = unpack2(a3);
            ulonglong2 v0, v1;
            v0.x = packf2(fmaxf(f0.x,0.f), fmaxf(f0.y,0.f));
            v0.y = packf2(fmaxf(f1.x,0.f), fmaxf(f1.y,0.f));
            v1.x = packf2(fmaxf(f2.x,0.f), fmaxf(f2.y,0.f));
            v1.y = packf2(fmaxf(f3.x,0.f), fmaxf(f3.y,0.f));
            ulonglong2* xr = (ulonglong2*)(sX + (g + 64*i) * RS + 8*cg);
            xr[0] = v0; xr[1] = v1;
        }
    }
    __syncthreads();

    // ---- phase 2: h[n][my 8 ch] = x[n][:] @ Wg[:, my 8 ch] ----
    ull acc[NPT][4];
    #pragma unroll
    for (int i = 0; i < NPT; i++)
        #pragma unroll
        for (int q = 0; q < 4; q++) acc[i][q] = 0ull;

    #pragma unroll
    for (int kc = 0; kc < 6; kc++) {
        float xs[NPT][4];
        #pragma unroll
        for (int i = 0; i < NPT; i++) {
            const ulonglong2 xc = *(const ulonglong2*)(sX + (g + 64*i) * RS + 4*kc);
            float2 lo = unpack2(xc.x), hi = unpack2(xc.y);
            xs[i][0] = lo.x; xs[i][1] = lo.y; xs[i][2] = hi.x; xs[i][3] = hi.y;
        }
        #pragma unroll
        for (int kk = 0; kk < 4; kk++) {
            const int k = 4*kc + kk;
            const ulonglong2* wr = (const ulonglong2*)(sWg + k * 24) + 2*cg;
            const ulonglong2 wA = wr[0], wB = wr[1];
            #pragma unroll
            for (int i = 0; i < NPT; i++) {
                const ull xp = pack2(xs[i][kk]);
                fma2(acc[i][0], xp, wA.x);
                fma2(acc[i][1], xp, wA.y);
                fma2(acc[i][2], xp, wB.x);
                fma2(acc[i][3], xp, wB.y);
            }
        }
    }

    // ---- attention dots for my head ----
    float aS[NPT], aD[NPT];
    {
        const ulonglong2 sa = ((const ulonglong2*)sAttS)[2*cg];
        const ulonglong2 sb = ((const ulonglong2*)sAttS)[2*cg + 1];
        const ulonglong2 da = ((const ulonglong2*)sAttD)[2*cg];
        const ulonglong2 db = ((const ulonglong2*)sAttD)[2*cg + 1];
        #pragma unroll
        for (int i = 0; i < NPT; i++) {
            ull r1 = 0ull, r2 = 0ull;
            fma2(r1, acc[i][0], sa.x); fma2(r1, acc[i][1], sa.y);
            fma2(r1, acc[i][2], sb.x); fma2(r1, acc[i][3], sb.y);
            fma2(r2, acc[i][0], da.x); fma2(r2, acc[i][1], da.y);
            fma2(r2, acc[i][2], db.x); fma2(r2, acc[i][3], db.y);
            float2 f1 = unpack2(r1), f2 = unpack2(r2);
            aS[i] = f1.x + f1.y;
            aD[i] = f2.x + f2.y;
        }
    }

    __syncthreads();   // all phase-2 x reads done before rows are overwritten with h

    // ---- publish h + a_src (only joints that are parents) ----
    #pragma unroll
    for (int i = 0; i < NPT; i++) {
        const int row = g + 64*i;
        const int j = row % NJ;
        if ((PARENT_MASK >> j) & 1u) {
            ulonglong2* hr = (ulonglong2*)(sX + row * RS + 8*cg);
            ulonglong2 v0, v1;
            v0.x = acc[i][0]; v0.y = acc[i][1];
            v1.x = acc[i][2]; v1.y = acc[i][3];
            hr[0] = v0; hr[1] = v1;
            sX[row * RS + 24 + cg] = aS[i];
        }
    }
    __syncthreads();

    // ---- epilogue: 2-edge softmax + aggregate + bias + relu + store ----
    const ulonglong2 bgA = ((const ulonglong2*)sbg)[2*cg];
    const ulonglong2 bgB = ((const ulonglong2*)sbg)[2*cg + 1];
    #pragma unroll
    for (int i = 0; i < NPT; i++) {
        const int row = g + 64*i;
        const int j = row % NJ;
        const int par = c_parent[j];
        const bool hasPar = (par >= 0);
        const int prow = row - j + (hasPar ? par : j);
        const float* pb = sX + prow * RS;
        const ulonglong2* ph = (const ulonglong2*)(pb + 8*cg);
        const ulonglong2 ph0 = ph[0], ph1 = ph[1];
        const float pas = pb[24 + cg];

        float es = aS[i] + aD[i];
        es = es >= 0.0f ? es : NEG * es;
        float ep = pas + aD[i];
        ep = ep >= 0.0f ? ep : NEG * ep;
        ep = hasPar ? ep : -1e30f;
        const float mx  = fmaxf(es, ep);
        const float ws  = __expf(es - mx);
        const float wp  = __expf(ep - mx);
        const float inv = __fdividef(1.0f, ws + wp);
        const float alS = ws * inv;
        const float alP = hasPar ? wp * inv : 0.0f;

        const ull s2 = pack2(alS), pp = pack2(alP);
        ull o0 = bgA.x, o1 = bgA.y, o2 = bgB.x, o3 = bgB.y;
        fma2(o0, s2, acc[i][0]); fma2(o0, pp, ph0.x);
        fma2(o1, s2, acc[i][1]); fma2(o1, pp, ph0.y);
        fma2(o2, s2, acc[i][2]); fma2(o2, pp, ph1.x);
        fma2(o3, s2, acc[i][3]); fma2(o3, pp, ph1.y);

        float2 f0 = unpack2(o0), f1 = unpack2(o1), f2 = unpack2(o2), f3 = unpack2(o3);
        float4* op = (float4*)(out + (base + (size_t)row) * 24 + 8*cg);
        float4 r0, r1;
        r0.x = fmaxf(f0.x, 0.f); r0.y = fmaxf(f0.y, 0.f);
        r0.z = fmaxf(f1.x, 0.f); r0.w = fmaxf(f1.y, 0.f);
        r1.x = fmaxf(f2.x, 0.f); r1.y = fmaxf(f2.y, 0.f);
        r1.z = fmaxf(f3.x, 0.f); r1.w = fmaxf(f3.y, 0.f);
        op[0] = r0; op[1] = r1;
    }
}

extern "C" void kernel_launch(void* const* d_in, const int* in_sizes, int n_in,
                              void* d_out, int out_size) {
    (void)n_in; (void)out_size;
    const float* src  = (const float*)d_in[0];
    const float* Wpre = (const float*)d_in[1];
    const float* bpre = (const float*)d_in[2];
    const float* Wg   = (const float*)d_in[3];
    const float* attS = (const float*)d_in[4];
    const float* attD = (const float*)d_in[5];
    const float* bg   = (const float*)d_in[6];

    const int nodes  = in_sizes[0] / 3;   // 3,145,728
    const int blocks = nodes / NPB;       // 8,192 (exact)

    gat_encoder_kernel<<<blocks, TPB>>>(src, Wpre, bpre, Wg, attS, attD, bg, (float*)d_out);
}